// round 3
// baseline (speedup 1.0000x reference)
#include <cuda_runtime.h>
#include <cuda_bf16.h>

#define BB   2
#define SS   256
#define INP  80
#define HH   128
#define GG   512      // 4*H
#define FF   256      // 2*H
#define NCC  40
#define WW   64       // WSEG
#define HID  100

typedef unsigned long long u64;

// ---------------- scratch (device globals; no allocation allowed) ----------------
__device__ float g_wihT [4][FF*GG];        // transposed input weights (layer0 uses first 80 rows)
__device__ u64   g_whhP [4][(HH/2)*GG];    // Whh pair-packed + transposed: [k2][g] -> (Whh[g][2k2],Whh[g][2k2+1])
__device__ u64   g_wsP  [3][128*128];      // w_s1 parts c/d/e pair-packed transposed: [k2][h]
__device__ float g_preF [SS*BB*GG];
__device__ float g_preB [SS*BB*GG];
__device__ float g_h0   [BB*SS*FF];
__device__ float g_rnn  [BB*SS*FF];
__device__ float g_cum  [BB*SS*FF];
__device__ float g_Pd   [BB*SS*HID];
__device__ float g_Pe   [BB*SS*HID];       // includes +b_s1
__device__ float g_sband[BB*SS*WW];        // sband[b][i][w], j = i-64+w

// ---------------- helpers ----------------
__device__ __forceinline__ void fma2(u64 &d, u64 a, u64 b) {
    asm("fma.rn.f32x2 %0, %1, %2, %0;" : "+l"(d) : "l"(a), "l"(b));
}
__device__ __forceinline__ float2 u2f(u64 v) {
    float2 f; asm("mov.b64 {%0,%1}, %2;" : "=f"(f.x), "=f"(f.y) : "l"(v)); return f;
}
__device__ __forceinline__ u64 f2u(float x, float y) {
    u64 v; asm("mov.b64 %0, {%1,%2};" : "=l"(v) : "f"(x), "f"(y)); return v;
}
__device__ __forceinline__ float sigm(float x) { return 1.f/(1.f + expf(-x)); }

// ---------------- prep: transposes / packing ----------------
__global__ void k_transpose(const float* __restrict__ w, float* __restrict__ wT, int cols) {
    int c = blockIdx.x, g = threadIdx.x;
    wT[c*GG + g] = w[g*cols + c];
}
__global__ void k_pack_whh(const float* __restrict__ w, u64* __restrict__ wp) {
    int k2 = blockIdx.x, g = threadIdx.x;
    wp[k2*GG + g] = f2u(w[g*HH + 2*k2], w[g*HH + 2*k2 + 1]);
}
__global__ void k_pack_ws1(const float* __restrict__ w) {
    int k2 = blockIdx.x, p = blockIdx.y, h = threadIdx.x;
    u64 v = 0ull;
    if (h < HID) v = f2u(w[h*768 + p*256 + 2*k2], w[h*768 + p*256 + 2*k2 + 1]);
    g_wsP[p][k2*128 + h] = v;
}

// ---------------- pre = x @ Wih^T + b  (S,B,512) ----------------
__global__ void k_pre(const float* __restrict__ xin, const float* __restrict__ wT,
                      const float* __restrict__ bias, float* __restrict__ pre, int Din) {
    __shared__ float xs[FF];
    int s = blockIdx.x, b = blockIdx.y, g = threadIdx.x;
    for (int i = g; i < Din; i += GG) xs[i] = xin[(b*SS + s)*Din + i];
    __syncthreads();
    float acc = bias[g];
    #pragma unroll 4
    for (int i = 0; i < Din; i++) acc += xs[i] * wT[i*GG + g];
    pre[(s*BB + b)*GG + g] = acc;
}

// ---------------- LSTM scan (one CTA per (b,dir)) ----------------
__global__ void k_scan(const float* __restrict__ preFp, const float* __restrict__ preBp,
                       const u64* __restrict__ wpF, const u64* __restrict__ wpB,
                       float* __restrict__ hout) {
    int b = blockIdx.x, dir = blockIdx.y, t = threadIdx.x;
    const float* pre = dir ? preBp : preFp;
    const u64*   wp  = (dir ? wpB : wpF) + t;
    __shared__ __align__(16) float hs[HH];
    __shared__ float cs[HH];
    __shared__ float gs[GG];
    if (t < HH) { hs[t] = 0.f; cs[t] = 0.f; }
    __syncthreads();
    const u64* h2 = (const u64*)hs;
    for (int step = 0; step < SS; ++step) {
        int s = dir ? (SS - 1 - step) : step;
        u64 a0 = 0ull, a1 = 0ull;
        #pragma unroll 8
        for (int k2 = 0; k2 < HH/2; k2 += 2) {
            fma2(a0, wp[(k2    )*GG], h2[k2    ]);
            fma2(a1, wp[(k2 + 1)*GG], h2[k2 + 1]);
        }
        float2 f0 = u2f(a0), f1 = u2f(a1);
        gs[t] = (f0.x + f0.y) + (f1.x + f1.y) + pre[(s*BB + b)*GG + t];
        __syncthreads();
        if (t < HH) {
            float ig = sigm(gs[t]);
            float fg = sigm(gs[t + HH]);
            float gg = tanhf(gs[t + 2*HH]);
            float og = sigm(gs[t + 3*HH]);
            float c  = fg*cs[t] + ig*gg;
            cs[t] = c;
            float h = og * tanhf(c);
            hs[t] = h;
            hout[(b*SS + s)*FF + dir*HH + t] = h;
        }
        __syncthreads();
    }
}

// ---------------- cls / bin MLPs ----------------
__global__ void k_clsbin(const float* __restrict__ rnn,
    const float* ac0, const float* __restrict__ wc1, const float* __restrict__ bc1,
    const float* ac1, const float* __restrict__ wc2, const float* __restrict__ bc2,
    const float* ab0, const float* __restrict__ wb1, const float* __restrict__ bb1,
    const float* ab1, const float* __restrict__ wb2, const float* __restrict__ bb2,
    float* __restrict__ out) {
    int s = blockIdx.x, b = blockIdx.y, t = threadIdx.x; // blockDim = 192
    __shared__ float xc[FF], xb[FF], hc[80], hb[80];
    float a0c = *ac0, a0b = *ab0;
    for (int k = t; k < FF; k += 192) {
        float v = rnn[(b*SS + s)*FF + k];
        xc[k] = v >= 0.f ? v : a0c*v;
        xb[k] = v >= 0.f ? v : a0b*v;
    }
    __syncthreads();
    if (t < 80) {
        float acc = bc1[t];
        const float* w = wc1 + t*FF;
        #pragma unroll 4
        for (int k = 0; k < FF; k++) acc += xc[k]*w[k];
        float a1 = *ac1;
        hc[t] = acc >= 0.f ? acc : a1*acc;
    } else if (t < 160) {
        int g = t - 80;
        float acc = bb1[g];
        const float* w = wb1 + g*FF;
        #pragma unroll 4
        for (int k = 0; k < FF; k++) acc += xb[k]*w[k];
        float a1 = *ab1;
        hb[g] = acc >= 0.f ? acc : a1*acc;
    }
    __syncthreads();
    if (t < NCC) {
        float acc = bc2[t];
        const float* w = wc2 + t*80;
        #pragma unroll 4
        for (int k = 0; k < 80; k++) acc += hc[k]*w[k];
        out[(b*SS + s)*NCC + t] = acc;
    } else if (t < NCC + 2) {
        int o = t - NCC;
        float acc = bb2[o];
        const float* w = wb2 + o*80;
        #pragma unroll 4
        for (int k = 0; k < 80; k++) acc += hb[k]*w[k];
        out[20480 + (b*SS + s)*2 + o] = acc;
    }
}

// ---------------- inclusive cumsum over s ----------------
__global__ void k_cum(const float* __restrict__ rnn) {
    int b = blockIdx.x, k = threadIdx.x; // blockDim = 256
    float run = 0.f;
    for (int t = 0; t < SS; t++) {
        run += rnn[(b*SS + t)*FF + k];
        g_cum[(b*SS + t)*FF + k] = run;
    }
}

// ---------------- Pd / Pe (rank-1 score-MLP terms) ----------------
__global__ void k_pdpe(const float* __restrict__ rnn, const float* as0, const float* __restrict__ bs1) {
    int s = blockIdx.x, b = blockIdx.y, t = threadIdx.x; // blockDim = 128
    __shared__ __align__(16) float xr[FF];
    float a0 = *as0;
    {
        float v0 = rnn[(b*SS + s)*FF + 2*t];
        float v1 = rnn[(b*SS + s)*FF + 2*t + 1];
        xr[2*t]     = v0 >= 0.f ? v0 : a0*v0;
        xr[2*t + 1] = v1 >= 0.f ? v1 : a0*v1;
    }
    __syncthreads();
    const u64* xp = (const u64*)xr;
    if (t < HID) {
        u64 d0 = 0ull, d1 = 0ull, e0 = 0ull, e1 = 0ull;
        #pragma unroll 8
        for (int k2 = 0; k2 < 128; k2 += 2) {
            fma2(d0, g_wsP[1][(k2    )*128 + t], xp[k2    ]);
            fma2(d1, g_wsP[1][(k2 + 1)*128 + t], xp[k2 + 1]);
            fma2(e0, g_wsP[2][(k2    )*128 + t], xp[k2    ]);
            fma2(e1, g_wsP[2][(k2 + 1)*128 + t], xp[k2 + 1]);
        }
        float2 fd0 = u2f(d0), fd1 = u2f(d1), fe0 = u2f(e0), fe1 = u2f(e1);
        g_Pd[(b*SS + s)*HID + t] = fd0.x + fd0.y + fd1.x + fd1.y;
        g_Pe[(b*SS + s)*HID + t] = fe0.x + fe0.y + fe1.x + fe1.y + bs1[t];
    }
}

// ---------------- banded score MLP ----------------
__global__ void k_scores(const float* as0, const float* as1,
                         const float* __restrict__ ws2, const float* bs2) {
    int i = blockIdx.x, b = blockIdx.y, jh = blockIdx.z, t = threadIdx.x; // blockDim = 128
    if (i == 0) return;
    __shared__ __align__(16) float cdf[FF];
    __shared__ float wsum[4];
    const u64* cd = (const u64*)cdf;
    float a0 = *as0, a1 = *as1, b2 = *bs2;
    const float* cumi = g_cum + (b*SS + i)*FF;
    float ci0 = cumi[2*t], ci1 = cumi[2*t + 1];
    float pei = (t < HID) ? g_Pe[(b*SS + i)*HID + t] : 0.f;
    float w2  = (t < HID) ? ws2[t] : 0.f;
    for (int wl = 0; wl < 32; ++wl) {
        int w = jh*32 + wl;
        int j = i - WW + w;
        if (j < 0) {                             // uniform across block
            if (t == 0) g_sband[(b*SS + i)*WW + w] = -1000000000.0f;
            continue;
        }
        const float* cumj = g_cum + (b*SS + j)*FF;
        float c0 = ci0 - cumj[2*t];
        float c1 = ci1 - cumj[2*t + 1];
        cdf[2*t]     = c0 >= 0.f ? c0 : a0*c0;
        cdf[2*t + 1] = c1 >= 0.f ? c1 : a0*c1;
        __syncthreads();
        float val = 0.f;
        if (t < HID) {
            u64 s0 = 0ull, s1 = 0ull;
            const u64* wrow = g_wsP[0] + t;
            #pragma unroll 8
            for (int k2 = 0; k2 < 128; k2 += 2) {
                fma2(s0, wrow[(k2    )*128], cd[k2    ]);
                fma2(s1, wrow[(k2 + 1)*128], cd[k2 + 1]);
            }
            float2 f0 = u2f(s0), f1 = u2f(s1);
            float hid = f0.x + f0.y + f1.x + f1.y + g_Pd[(b*SS + j)*HID + t] + pei;
            float ph  = hid >= 0.f ? hid : a1*hid;
            val = ph * w2;
        }
        for (int off = 16; off; off >>= 1) val += __shfl_down_sync(0xffffffffu, val, off);
        if ((t & 31) == 0) wsum[t >> 5] = val;
        __syncthreads();
        if (t == 0) g_sband[(b*SS + i)*WW + w] = wsum[0] + wsum[1] + wsum[2] + wsum[3] + b2;
        __syncthreads();
    }
}

// ---------------- DP + backtrack (one warp per batch row) ----------------
__global__ void k_dp(const int* __restrict__ lengths, float* __restrict__ out) {
    __shared__ float best[BB][SS];
    __shared__ int   bp[BB][SS];
    int t = threadIdx.x;          // blockDim = 64
    int b = t >> 5, lane = t & 31;
    for (int idx = t; idx < BB*SS; idx += 64) best[idx >> 8][idx & 255] = 0.f;
    for (int idx = t; idx < BB*SS; idx += 64) out[21504 + idx] = 0.f;   // zero bmask
    if (t < BB) bp[t][0] = 0;
    __syncthreads();
    for (int i = 1; i < SS; i++) {
        int w1 = lane, w2 = lane + 32;
        int j1 = i - WW + w1, j2 = i - WW + w2;
        float c1 = (j1 >= 0) ? best[b][j1] + g_sband[(b*SS + i)*WW + w1] : -1000000000.0f;
        float c2 = (j2 >= 0) ? best[b][j2] + g_sband[(b*SS + i)*WW + w2] : -1000000000.0f;
        float v; int jj;
        if (c2 > c1) { v = c2; jj = j2; } else { v = c1; jj = j1; }   // tie -> smaller j
        for (int off = 16; off; off >>= 1) {
            float ov = __shfl_down_sync(0xffffffffu, v,  off);
            int   oj = __shfl_down_sync(0xffffffffu, jj, off);
            if (ov > v || (ov == v && oj < jj)) { v = ov; jj = oj; }
        }
        if (lane == 0) { best[b][i] = v; bp[b][i] = jj; }
        __syncwarp();
    }
    __syncthreads();
    if (t < BB) {
        int cur = lengths[t] - 1;
        if (cur < 0) cur = 0;
        float acc = 0.f;
        while (true) {
            out[21504 + t*SS + cur] = 1.f;
            if (cur == 0) break;
            int prev = bp[t][cur];
            acc += g_sband[(t*SS + cur)*WW + (prev - (cur - WW))];
            cur = prev;
        }
        out[22016 + t] = acc;
    }
}

// ---------------- launch ----------------
extern "C" void kernel_launch(void* const* d_in, const int* in_sizes, int n_in,
                              void* d_out, int out_size) {
    (void)in_sizes; (void)n_in; (void)out_size;
    const float* x        = (const float*)d_in[0];
    const int*   lengths  = (const int*)  d_in[1];
    const float* wih[4]   = {(const float*)d_in[2], (const float*)d_in[5],
                             (const float*)d_in[8], (const float*)d_in[11]};
    const float* whh[4]   = {(const float*)d_in[3], (const float*)d_in[6],
                             (const float*)d_in[9], (const float*)d_in[12]};
    const float* bl[4]    = {(const float*)d_in[4], (const float*)d_in[7],
                             (const float*)d_in[10], (const float*)d_in[13]};
    const float* a_s0 = (const float*)d_in[14];
    const float* w_s1 = (const float*)d_in[15];
    const float* b_s1 = (const float*)d_in[16];
    const float* a_s1 = (const float*)d_in[17];
    const float* w_s2 = (const float*)d_in[18];
    const float* b_s2 = (const float*)d_in[19];
    const float* a_c0 = (const float*)d_in[20];
    const float* w_c1 = (const float*)d_in[21];
    const float* b_c1 = (const float*)d_in[22];
    const float* a_c1 = (const float*)d_in[23];
    const float* w_c2 = (const float*)d_in[24];
    const float* b_c2 = (const float*)d_in[25];
    const float* a_b0 = (const float*)d_in[26];
    const float* w_b1 = (const float*)d_in[27];
    const float* b_b1 = (const float*)d_in[28];
    const float* a_b1 = (const float*)d_in[29];
    const float* w_b2 = (const float*)d_in[30];
    const float* b_b2 = (const float*)d_in[31];
    float* out = (float*)d_out;

    float *wihT, *preF, *preB, *h0, *rnn;
    u64 *whhP;
    cudaGetSymbolAddress((void**)&wihT, g_wihT);
    cudaGetSymbolAddress((void**)&whhP, g_whhP);
    cudaGetSymbolAddress((void**)&preF, g_preF);
    cudaGetSymbolAddress((void**)&preB, g_preB);
    cudaGetSymbolAddress((void**)&h0,   g_h0);
    cudaGetSymbolAddress((void**)&rnn,  g_rnn);

    const int dins[2] = {INP, FF};
    for (int m = 0; m < 4; m++) {
        int Din = dins[m >> 1];
        k_transpose<<<Din, GG>>>(wih[m], wihT + m*FF*GG, Din);
        k_pack_whh<<<HH/2, GG>>>(whh[m], whhP + m*(HH/2)*GG);
    }
    k_pack_ws1<<<dim3(128, 3), 128>>>(w_s1);

    dim3 gpre(SS, BB);
    // layer 0
    k_pre<<<gpre, GG>>>(x, wihT + 0*FF*GG, bl[0], preF, INP);
    k_pre<<<gpre, GG>>>(x, wihT + 1*FF*GG, bl[1], preB, INP);
    k_scan<<<dim3(BB, 2), GG>>>(preF, preB, whhP + 0*(HH/2)*GG, whhP + 1*(HH/2)*GG, h0);
    // layer 1
    k_pre<<<gpre, GG>>>(h0, wihT + 2*FF*GG, bl[2], preF, FF);
    k_pre<<<gpre, GG>>>(h0, wihT + 3*FF*GG, bl[3], preB, FF);
    k_scan<<<dim3(BB, 2), GG>>>(preF, preB, whhP + 2*(HH/2)*GG, whhP + 3*(HH/2)*GG, rnn);

    k_clsbin<<<gpre, 192>>>(rnn, a_c0, w_c1, b_c1, a_c1, w_c2, b_c2,
                                 a_b0, w_b1, b_b1, a_b1, w_b2, b_b2, out);
    k_cum<<<BB, FF>>>(rnn);
    k_pdpe<<<gpre, 128>>>(rnn, a_s0, b_s1);
    k_scores<<<dim3(SS, BB, 2), 128>>>(a_s0, a_s1, w_s2, b_s2);
    k_dp<<<1, 64>>>(lengths, out);
}